// round 15
// baseline (speedup 1.0000x reference)
#include <cuda_runtime.h>
#include <cuda_fp16.h>
#include <math.h>
#include <stdint.h>

#define NN 4096
#define EE 65536

// ------------------- scratch (static device globals; no allocs) -------------
__device__ float g_P[NN * 1024];   // split-K=2 partials (reduced in k_padd)
__device__ float g_A[NN * 256];
__device__ float g_B[NN * 256];
__device__ float g_C[NN * 256];
__device__ float g_D[NN * 128];
__device__ float g_E[NN * 128];
__device__ float g_dinv[NN];
__device__ int   g_rowptr[NN + 1];
__device__ int   g_adj[EE];
// packed fp16 fragment-major operands (stored as uint32 = half2)
__device__ uint32_t g_Xt[NN * NN / 2];
__device__ uint32_t g_Wt[NN * 512 / 2];
__device__ uint32_t g_Ht[NN * 128 / 2];
__device__ uint32_t g_OWt[128 * 16384 / 2];

__device__ __forceinline__ uint32_t pack2h(float a, float b) {
    uint32_t lo = __half_as_ushort(__float2half_rn(a));
    uint32_t hi = __half_as_ushort(__float2half_rn(b));
    return lo | (hi << 16);
}

// ---------- fused CSR build + adjacency fill (1 block, 1024 thr) ------------
__global__ void k_csr(const int* __restrict__ src, const int* __restrict__ dst) {
    __shared__ int sc[NN];
    __shared__ int ts[1024];
    int t = threadIdx.x;
    ((int4*)sc)[t] = make_int4(0, 0, 0, 0);
    __syncthreads();
    for (int e = t; e < EE; e += 1024) atomicAdd(&sc[dst[e]], 1);
    __syncthreads();
    int4 c = ((int4*)sc)[t];
    int s = c.x + c.y + c.z + c.w;
    ts[t] = s;
    __syncthreads();
    for (int off = 1; off < 1024; off <<= 1) {
        int x = (t >= off) ? ts[t - off] : 0;
        __syncthreads();
        ts[t] += x;
        __syncthreads();
    }
    int excl = ts[t] - s;
    int p0 = excl, p1 = excl + c.x, p2 = p1 + c.y, p3 = p2 + c.z;
    g_rowptr[4 * t + 0] = p0;
    g_rowptr[4 * t + 1] = p1;
    g_rowptr[4 * t + 2] = p2;
    g_rowptr[4 * t + 3] = p3;
    g_dinv[4 * t + 0] = rsqrtf((float)(c.x + 1));
    g_dinv[4 * t + 1] = rsqrtf((float)(c.y + 1));
    g_dinv[4 * t + 2] = rsqrtf((float)(c.z + 1));
    g_dinv[4 * t + 3] = rsqrtf((float)(c.w + 1));
    if (t == 1023) g_rowptr[NN] = ts[t];
    __syncthreads();
    // reuse sc as fill cursors
    sc[4 * t + 0] = p0;
    sc[4 * t + 1] = p1;
    sc[4 * t + 2] = p2;
    sc[4 * t + 3] = p3;
    __syncthreads();
    for (int e = t; e < EE; e += 1024) {
        int pos = atomicAdd(&sc[dst[e]], 1);
        g_adj[pos] = src[e];
    }
}

// ---- reduce split-K partials: P0 += P1 --------------------------------------
__global__ void k_padd() {
    int i = blockIdx.x * blockDim.x + threadIdx.x;
    if (i >= NN * 128) return;
    float4 a = ((float4*)g_P)[i];
    float4 b = ((const float4*)g_P)[NN * 128 + i];
    a.x += b.x; a.y += b.y; a.z += b.z; a.w += b.w;
    ((float4*)g_P)[i] = a;
}

// ---------------------- gather-based aggregations (unroll x2) ---------------
__global__ void k_sage_gather(const float* __restrict__ bl) {
    int t = blockIdx.x * blockDim.x + threadIdx.x;
    if (t >= NN * 64) return;
    int v = t >> 6;
    int q = t & 63;
    int beg = g_rowptr[v], end = g_rowptr[v + 1];
    const float4* P4 = (const float4*)g_P;
    float4 a0 = make_float4(0.f, 0.f, 0.f, 0.f);
    float4 a1 = make_float4(0.f, 0.f, 0.f, 0.f);
    int i = beg;
    for (; i + 1 < end; i += 2) {
        int s0 = g_adj[i];
        int s1 = g_adj[i + 1];
        float4 p0 = P4[(size_t)s0 * 128 + q];
        float4 p1 = P4[(size_t)s1 * 128 + q];
        a0.x += p0.x; a0.y += p0.y; a0.z += p0.z; a0.w += p0.w;
        a1.x += p1.x; a1.y += p1.y; a1.z += p1.z; a1.w += p1.w;
    }
    if (i < end) {
        int s0 = g_adj[i];
        float4 p0 = P4[(size_t)s0 * 128 + q];
        a0.x += p0.x; a0.y += p0.y; a0.z += p0.z; a0.w += p0.w;
    }
    float4 acc = make_float4(a0.x + a1.x, a0.y + a1.y, a0.z + a1.z, a0.w + a1.w);
    float inv = 1.0f / fmaxf((float)(end - beg), 1.0f);
    float4 b = ((const float4*)bl)[q];
    float4 pr = P4[(size_t)v * 128 + 64 + q];
    float4 r;
    r.x = fmaxf(acc.x * inv + b.x + pr.x, 0.f);
    r.y = fmaxf(acc.y * inv + b.y + pr.y, 0.f);
    r.z = fmaxf(acc.z * inv + b.z + pr.z, 0.f);
    r.w = fmaxf(acc.w * inv + b.w + pr.w, 0.f);
    ((float4*)g_B)[(size_t)v * 64 + q] = r;
}

__global__ void k_gcn_gather(const float* __restrict__ hw, const float* __restrict__ bias,
                             float* __restrict__ out, int hqsh) {
    int t = blockIdx.x * blockDim.x + threadIdx.x;
    if (t >= (NN << hqsh)) return;
    int v = t >> hqsh;
    int q = t & ((1 << hqsh) - 1);
    int Hq = 1 << hqsh;
    int beg = g_rowptr[v], end = g_rowptr[v + 1];
    float dv = g_dinv[v];
    const float4* H4 = (const float4*)hw;
    float4 self = H4[(size_t)v * Hq + q];
    float dv2 = dv * dv;
    float4 a0 = make_float4(dv2 * self.x, dv2 * self.y, dv2 * self.z, dv2 * self.w);
    float4 a1 = make_float4(0.f, 0.f, 0.f, 0.f);
    int i = beg;
    for (; i + 1 < end; i += 2) {
        int s0 = g_adj[i];
        int s1 = g_adj[i + 1];
        float n0 = dv * g_dinv[s0];
        float n1 = dv * g_dinv[s1];
        float4 p0 = H4[(size_t)s0 * Hq + q];
        float4 p1 = H4[(size_t)s1 * Hq + q];
        a0.x += n0 * p0.x; a0.y += n0 * p0.y; a0.z += n0 * p0.z; a0.w += n0 * p0.w;
        a1.x += n1 * p1.x; a1.y += n1 * p1.y; a1.z += n1 * p1.z; a1.w += n1 * p1.w;
    }
    if (i < end) {
        int s0 = g_adj[i];
        float n0 = dv * g_dinv[s0];
        float4 p0 = H4[(size_t)s0 * Hq + q];
        a0.x += n0 * p0.x; a0.y += n0 * p0.y; a0.z += n0 * p0.z; a0.w += n0 * p0.w;
    }
    float4 b = ((const float4*)bias)[q];
    float4 r;
    r.x = fmaxf(a0.x + a1.x + b.x, 0.f);
    r.y = fmaxf(a0.y + a1.y + b.y, 0.f);
    r.z = fmaxf(a0.z + a1.z + b.z, 0.f);
    r.w = fmaxf(a0.w + a1.w + b.w, 0.f);
    ((float4*)out)[(size_t)v * Hq + q] = r;
}

// ---- pack A to fp16 fragment-major, smem-staged (one block per 128x32 tile) -
// Output layout per (br, kt): 2048 u32 at index q: reg=q&3, lane=(q>>2)&31,
// t8=(q>>7)&7, s=q>>10; qm=lane>>2, qk=lane&3;
//   m_local = t8*16 + qm + (reg&1)*8,  k_local = s*16 + 2*qk + (reg&2)*4.
__global__ void __launch_bounds__(256)
k_packAh(const float* __restrict__ in, uint32_t* __restrict__ out, int lda) {
    __shared__ float st[128][33];
    int b = blockIdx.x;
    int ktp = lda >> 5;          // lda == K for our callers (x: 4096, h5: 128)
    int br = b / ktp;
    int kt = b - br * ktp;
    int tid = threadIdx.x;

    // load 128x32 tile, 16 consecutive floats per thread
    int row = tid >> 1;
    int off = (tid & 1) << 4;
    const float* srcp = in + (size_t)(br * 128 + row) * lda + kt * 32 + off;
    #pragma unroll
    for (int j = 0; j < 4; j++) {
        float4 v = *(const float4*)(srcp + j * 4);
        st[row][off + j * 4 + 0] = v.x;
        st[row][off + j * 4 + 1] = v.y;
        st[row][off + j * 4 + 2] = v.z;
        st[row][off + j * 4 + 3] = v.w;
    }
    __syncthreads();

    uint32_t* outp = out + (size_t)b * 2048;
    #pragma unroll
    for (int i = 0; i < 8; i++) {
        int o = tid + i * 256;
        int reg = o & 3;
        int lane = (o >> 2) & 31;
        int t8 = (o >> 7) & 7;
        int s = o >> 10;
        int qm = lane >> 2;
        int qk = lane & 3;
        int ml = t8 * 16 + qm + (reg & 1) * 8;
        int kl = s * 16 + 2 * qk + (reg & 2) * 4;
        outp[o] = pack2h(st[ml][kl], st[ml][kl + 1]);
    }
}

// ---- pack B to fp16 fragment-major, PAIRED n-fragments (BN=128) ------------
__global__ void k_packBh(const float* __restrict__ B0, const float* __restrict__ B1,
                         int nsplit, int K, int ldb, uint32_t* __restrict__ out) {
    int o = blockIdx.x * blockDim.x + threadIdx.x;
    int ktp = K >> 5;
    int perBc = ktp << 11;
    int bc = o / perBc;
    int r = o - bc * perBc;
    int kt = r >> 11;
    int q = r & 2047;
    int reg = q & 3;
    int lane = (q >> 2) & 31;
    int u2 = (q >> 7) & 7;
    int s = q >> 10;
    int qm = lane >> 2;
    int qk = lane & 3;
    int n = bc * 128 + u2 * 16 + qm + ((reg >> 1) & 1) * 8;
    int k = kt * 32 + s * 16 + 2 * qk + (reg & 1) * 8;
    const float* src = B0;
    if (n >= nsplit) { src = B1; n -= nsplit; }
    float v0 = src[(size_t)k * ldb + n];
    float v1 = src[(size_t)(k + 1) * ldb + n];
    out[o] = pack2h(v0, v1);
}

// ------------------- fp32 SIMT GEMM, 64x64x16 tiles (GCN layers) ------------
__global__ void __launch_bounds__(256, 4)
sgemm64(int M, int N, int K,
        const float* __restrict__ A, int lda,
        const float* __restrict__ B, int ldb,
        float* __restrict__ C, int ldc)
{
    const int BK = 16;
    __shared__ float As[2][BK][64];
    __shared__ float Bs[2][BK][64];

    int tid = threadIdx.x;
    int tx = tid & 15;
    int ty = tid >> 4;
    int row0 = blockIdx.y * 64;
    int col0 = blockIdx.x * 64;

    int am = tid >> 2;
    int ak = (tid & 3) << 2;
    int bk = tid >> 4;
    int bn = (tid & 15) << 2;

    const float* Aptr = A + (size_t)(row0 + am) * lda + ak;
    const float* Bptr = B + (size_t)bk * ldb + col0 + bn;
    size_t bstep = (size_t)BK * ldb;

    float4 av = *(const float4*)Aptr;
    float4 bv = *(const float4*)Bptr;
    As[0][ak + 0][am] = av.x;
    As[0][ak + 1][am] = av.y;
    As[0][ak + 2][am] = av.z;
    As[0][ak + 3][am] = av.w;
    *(float4*)&Bs[0][bk][bn] = bv;
    __syncthreads();

    float acc[4][4];
    #pragma unroll
    for (int i = 0; i < 4; i++)
        #pragma unroll
        for (int j = 0; j < 4; j++) acc[i][j] = 0.0f;

    int ntiles = K / BK;
    for (int t = 0; t < ntiles; t++) {
        int buf = t & 1;
        if (t + 1 < ntiles) {
            av = *(const float4*)(Aptr + (size_t)(t + 1) * BK);
            bv = *(const float4*)(Bptr + (size_t)(t + 1) * bstep);
        }
        #pragma unroll
        for (int k = 0; k < BK; k++) {
            float a[4], b[4];
            *(float4*)&a[0] = *(float4*)&As[buf][k][ty * 4];
            *(float4*)&b[0] = *(float4*)&Bs[buf][k][tx * 4];
            #pragma unroll
            for (int i = 0; i < 4; i++)
                #pragma unroll
                for (int j = 0; j < 4; j++)
                    acc[i][j] = fmaf(a[i], b[j], acc[i][j]);
        }
        if (t + 1 < ntiles) {
            int nb = buf ^ 1;
            As[nb][ak + 0][am] = av.x;
            As[nb][ak + 1][am] = av.y;
            As[nb][ak + 2][am] = av.z;
            As[nb][ak + 3][am] = av.w;
            *(float4*)&Bs[nb][bk][bn] = bv;
            __syncthreads();
        }
    }

    #pragma unroll
    for (int i = 0; i < 4; i++) {
        int gm = row0 + ty * 4 + i;
        int gn = col0 + tx * 4;
        *(float4*)&C[(size_t)gm * ldc + gn] =
            make_float4(acc[i][0], acc[i][1], acc[i][2], acc[i][3]);
    }
}

// ---------------- fused fc1+fc2: C = relu(relu(D@W1+b1)@W2+b2) --------------
__global__ void __launch_bounds__(256, 2)
k_fc12(const float* __restrict__ D,
       const float* __restrict__ W1, const float* __restrict__ b1,
       const float* __restrict__ W2, const float* __restrict__ b2,
       float* __restrict__ C)
{
    __shared__ float As[16][64];
    __shared__ float Bs[16][128];
    __shared__ float hs[64][132];

    int tid = threadIdx.x;
    int tx = tid & 15;
    int ty = tid >> 4;
    int row0 = blockIdx.x * 64;
    int am = tid >> 2;
    int ak = (tid & 3) << 2;

    float acc[4][8];
    #pragma unroll
    for (int i = 0; i < 4; i++)
        #pragma unroll
        for (int j = 0; j < 8; j++) acc[i][j] = 0.0f;

    for (int t = 0; t < 8; t++) {
        __syncthreads();
        {
            float4 av = *(const float4*)&D[(size_t)(row0 + am) * 128 + t * 16 + ak];
            As[ak + 0][am] = av.x;
            As[ak + 1][am] = av.y;
            As[ak + 2][am] = av.z;
            As[ak + 3][am] = av.w;
            #pragma unroll
            for (int l = 0; l < 2; l++) {
                int i = tid + l * 256;
                int bk = i >> 5;
                int bn = (i & 31) << 2;
                *(float4*)&Bs[bk][bn] = *(const float4*)&W1[(size_t)(t * 16 + bk) * 128 + bn];
            }
        }
        __syncthreads();
        #pragma unroll
        for (int k = 0; k < 16; k++) {
            float a[4], b[8];
            *(float4*)&a[0] = *(float4*)&As[k][ty * 4];
            *(float4*)&b[0] = *(float4*)&Bs[k][tx * 8];
            *(float4*)&b[4] = *(float4*)&Bs[k][tx * 8 + 4];
            #pragma unroll
            for (int i = 0; i < 4; i++)
                #pragma unroll
                for (int j = 0; j < 8; j++)
                    acc[i][j] = fmaf(a[i], b[j], acc[i][j]);
        }
    }
    __syncthreads();
    #pragma unroll
    for (int i = 0; i < 4; i++)
        #pragma unroll
        for (int j = 0; j < 8; j++)
            hs[ty * 4 + i][tx * 8 + j] = fmaxf(acc[i][j] + b1[tx * 8 + j], 0.0f);

    #pragma unroll
    for (int i = 0; i < 4; i++)
        #pragma unroll
        for (int j = 0; j < 8; j++) acc[i][j] = 0.0f;

    for (int t = 0; t < 8; t++) {
        __syncthreads();
        #pragma unroll
        for (int l = 0; l < 2; l++) {
            int i = tid + l * 256;
            int bk = i >> 5;
            int bn = (i & 31) << 2;
            *(float4*)&Bs[bk][bn] = *(const float4*)&W2[(size_t)(t * 16 + bk) * 128 + bn];
        }
        __syncthreads();
        #pragma unroll
        for (int k = 0; k < 16; k++) {
            int kk = t * 16 + k;
            float b[8];
            *(float4*)&b[0] = *(float4*)&Bs[k][tx * 8];
            *(float4*)&b[4] = *(float4*)&Bs[k][tx * 8 + 4];
            #pragma unroll
            for (int i = 0; i < 4; i++) {
                float a = hs[ty * 4 + i][kk];
                #pragma unroll
                for (int j = 0; j < 8; j++)
                    acc[i][j] = fmaf(a, b[j], acc[i][j]);
            }
        }
    }
    #pragma unroll
    for (int i = 0; i < 4; i++) {
        int gm = row0 + ty * 4 + i;
        #pragma unroll
        for (int j = 0; j < 8; j += 4) {
            int gn = tx * 8 + j;
            float4 v;
            v.x = fmaxf(acc[i][j + 0] + b2[gn + 0], 0.f);
            v.y = fmaxf(acc[i][j + 1] + b2[gn + 1], 0.f);
            v.z = fmaxf(acc[i][j + 2] + b2[gn + 2], 0.f);
            v.w = fmaxf(acc[i][j + 3] + b2[gn + 3], 0.f);
            *(float4*)&C[(size_t)gm * 128 + gn] = v;
        }
    }
}

// ------------- fp16 mma.sync GEMM (m16n8k16), cp.async 4-stage ---------------
__device__ __forceinline__ void mma_f16(float* c, const uint32_t* a, const uint32_t* b) {
    asm volatile(
        "mma.sync.aligned.m16n8k16.row.col.f32.f16.f16.f32 "
        "{%0,%1,%2,%3}, {%4,%5,%6,%7}, {%8,%9}, {%0,%1,%2,%3};"
        : "+f"(c[0]), "+f"(c[1]), "+f"(c[2]), "+f"(c[3])
        : "r"(a[0]), "r"(a[1]), "r"(a[2]), "r"(a[3]), "r"(b[0]), "r"(b[1]));
}
__device__ __forceinline__ void cp16(uint32_t s, const void* g) {
    asm volatile("cp.async.cg.shared.global [%0], [%1], 16;" :: "r"(s), "l"(g));
}

__global__ void __launch_bounds__(256, 2)
gemm_fp16p(int ktiles, int ktstride, size_t czstride,
           const uint32_t* __restrict__ At,
           const uint32_t* __restrict__ Bt,
           float* __restrict__ C, int ldc,
           const float* __restrict__ bias)
{
    const int MFRAG = 4;
    const int NFRAG = 4;
    const int TILE = 2048;

    extern __shared__ __align__(16) uint32_t smem[];
    uint32_t* AsF = smem;
    uint32_t* BsF = smem + 4 * TILE;

    int tid = threadIdx.x;
    int lane = tid & 31;
    int warp = tid >> 5;
    int warp_m = warp >> 2;
    int warp_n = warp & 3;

    int br = blockIdx.y;
    int bc = blockIdx.x;
    int kt0 = blockIdx.z * ktiles;

    const uint4* Ab = (const uint4*)At + ((size_t)br * ktstride + kt0) * (TILE / 4);
    const uint4* Bb = (const uint4*)Bt + ((size_t)bc * ktstride + kt0) * (TILE / 4);
    C += (size_t)blockIdx.z * czstride;

    uint32_t sbase = (uint32_t)__cvta_generic_to_shared(smem);
    uint32_t sb_b = sbase + 4 * TILE * 4;

    auto issue = [&](int t) {
        int slot = t & 3;
        const uint4* An = Ab + (size_t)t * (TILE / 4);
        const uint4* Bn = Bb + (size_t)t * (TILE / 4);
        uint32_t a0 = sbase + slot * (TILE * 4) + tid * 16;
        cp16(a0, An + tid);
        cp16(a0 + 4096, An + tid + 256);
        uint32_t b0 = sb_b + slot * (TILE * 4) + tid * 16;
        cp16(b0, Bn + tid);
        cp16(b0 + 4096, Bn + tid + 256);
        asm volatile("cp.async.commit_group;" ::: "memory");
    };

    issue(0);
    if (ktiles > 1) issue(1);
    if (ktiles > 2) issue(2);

    float acc[MFRAG][NFRAG][4];
    #pragma unroll
    for (int mi = 0; mi < MFRAG; mi++)
        #pragma unroll
        for (int ni = 0; ni < NFRAG; ni++)
            #pragma unroll
            for (int j = 0; j < 4; j++) acc[mi][ni][j] = 0.0f;

    for (int t = 0; t < ktiles; t++) {
        int rem = ktiles - 1 - t;
        if (rem >= 2)      asm volatile("cp.async.wait_group 2;" ::: "memory");
        else if (rem == 1) asm volatile("cp.async.wait_group 1;" ::: "memory");
        else               asm volatile("cp.async.wait_group 0;" ::: "memory");
        __syncthreads();

        if (t + 3 < ktiles) issue(t + 3);

        int slot = t & 3;
        const uint32_t* As = AsF + slot * TILE;
        const uint32_t* Bs = BsF + slot * TILE;

        #pragma unroll
        for (int s = 0; s < 2; s++) {
            uint32_t afr[MFRAG][4];
            uint32_t bfr[NFRAG][2];
            #pragma unroll
            for (int mi = 0; mi < MFRAG; mi++) {
                int t8 = warp_m * MFRAG + mi;
                uint4 fa = *(const uint4*)&As[(((s << 3) + t8) * 32 + lane) * 4];
                afr[mi][0] = fa.x; afr[mi][1] = fa.y;
                afr[mi][2] = fa.z; afr[mi][3] = fa.w;
            }
            #pragma unroll
            for (int ni2 = 0; ni2 < NFRAG / 2; ni2++) {
                int u2 = warp_n * (NFRAG / 2) + ni2;
                uint4 fb = *(const uint4*)&Bs[(((s << 3) + u2) * 32 + lane) * 4];
                bfr[2 * ni2][0]     = fb.x;
                bfr[2 * ni2][1]     = fb.y;
                bfr[2 * ni2 + 1][0] = fb.z;
                bfr[2 * ni2 + 1][1] = fb.w;
            }
            #pragma unroll
            for (int mi = 0; mi < MFRAG; mi++)
                #pragma unroll
                for (int ni = 0; ni < NFRAG; ni++)
                    mma_f16(acc[mi][ni], afr[mi], bfr[ni]);
        }
    }

    int qm = lane >> 2;
    int qk = lane & 3;
    #pragma unroll
    for (int mi = 0; mi < MFRAG; mi++) {
        int r = br * 128 + warp_m * 64 + mi * 16 + qm;
        #pragma unroll
        for (int ni = 0; ni < NFRAG; ni++) {
            int c = bc * 128 + warp_n * 32 + ni * 8 + 2 * qk;
            float2 v0 = make_float2(acc[mi][ni][0], acc[mi][ni][1]);
            float2 v1 = make_float2(acc[mi][ni][2], acc[mi][ni][3]);
            if (bias) {
                float2 bb = *(const float2*)&bias[c];
                v0.x += bb.x; v0.y += bb.y;
                v1.x += bb.x; v1.y += bb.y;
            }
            *(float2*)&C[(size_t)r * ldc + c] = v0;
            *(float2*)&C[(size_t)(r + 8) * ldc + c] = v1;
        }
    }
}

// ------------------------------ host orchestration ---------------------------
extern "C" void kernel_launch(void* const* d_in, const int* in_sizes, int n_in,
                              void* d_out, int out_size)
{
    const float* x       = (const float*)d_in[0];
    const int*   eidx    = (const int*)  d_in[1];
    const float* sage_Wl = (const float*)d_in[2];
    const float* sage_bl = (const float*)d_in[3];
    const float* sage_Wr = (const float*)d_in[4];
    const float* gcn1_W  = (const float*)d_in[5];
    const float* gcn1_b  = (const float*)d_in[6];
    const float* gcn2_W  = (const float*)d_in[7];
    const float* gcn2_b  = (const float*)d_in[8];
    const float* fc1_W   = (const float*)d_in[9];
    const float* fc1_b   = (const float*)d_in[10];
    const float* fc2_W   = (const float*)d_in[11];
    const float* fc2_b   = (const float*)d_in[12];
    const float* out_W   = (const float*)d_in[13];
    const float* out_b   = (const float*)d_in[14];
    float* out = (float*)d_out;

    const int* src = eidx;
    const int* dst = eidx + EE;

    float *P, *A, *B, *C, *D, *E;
    uint32_t *Xt, *Wt, *Ht, *OWt;
    cudaGetSymbolAddress((void**)&P, g_P);
    cudaGetSymbolAddress((void**)&A, g_A);
    cudaGetSymbolAddress((void**)&B, g_B);
    cudaGetSymbolAddress((void**)&C, g_C);
    cudaGetSymbolAddress((void**)&D, g_D);
    cudaGetSymbolAddress((void**)&E, g_E);
    cudaGetSymbolAddress((void**)&Xt, g_Xt);
    cudaGetSymbolAddress((void**)&Wt, g_Wt);
    cudaGetSymbolAddress((void**)&Ht, g_Ht);
    cudaGetSymbolAddress((void**)&OWt, g_OWt);

    const int TPB = 256;
    const int GSMEM = 8 * 2048 * 4;   // 64KB: 4-slot A+B ring
    cudaFuncSetAttribute(gemm_fp16p, cudaFuncAttributeMaxDynamicSharedMemorySize, GSMEM);

    // fused CSR build + fill
    k_csr<<<1, 1024>>>(src, dst);

    // pack operands (fp16 fragment-major); packAh is smem-staged
    k_packAh<<<(NN / 128) * (NN / 32), 256>>>(x, Xt, NN);
    k_packBh<<<NN * 512 / 2 / TPB, TPB>>>(sage_Wl, sage_Wr, 256, NN, 256, Wt);
    k_packBh<<<128 * 16384 / 2 / TPB, TPB>>>(out_W, out_W, 16384, 128, 16384, OWt);

    // P = x @ [Wl | Wr], split-K=2: grid (4,32,2), 64 k-tiles of 32 each
    {
        dim3 grid(512 / 128, NN / 128, 2);
        gemm_fp16p<<<grid, 256, GSMEM>>>(64, 128, (size_t)NN * 512, Xt, Wt, P, 512, nullptr);
    }
    k_padd<<<NN * 128 / TPB, TPB>>>();

    // SAGE (gather, fused combine) -> B
    k_sage_gather<<<NN * 64 / TPB, TPB>>>(sage_bl);

    // GCN1: hw -> C, gather+bias+relu -> A
    {
        dim3 grid(256 / 64, NN / 64);
        sgemm64<<<grid, 256>>>(NN, 256, 256, B, 256, gcn1_W, 256, C, 256);
    }
    k_gcn_gather<<<NN * 64 / TPB, TPB>>>(C, gcn1_b, A, 6);

    // GCN2: hw -> D, gather+bias+relu -> E
    {
        dim3 grid(128 / 64, NN / 64);
        sgemm64<<<grid, 256>>>(NN, 128, 256, A, 256, gcn2_W, 128, D, 128);
    }
    k_gcn_gather<<<NN * 32 / TPB, TPB>>>(D, gcn2_b, E, 5);

    // fused fc1+fc2: E -> C
    k_fc12<<<NN / 64, 256>>>(E, fc1_W, fc1_b, fc2_W, fc2_b, C);

    // head GEMM (4096 x 16384 x 128): 4 k-tiles
    k_packAh<<<(NN / 128) * (128 / 32), 256>>>(C, Ht, 128);
    {
        dim3 grid(16384 / 128, NN / 128, 1);
        gemm_fp16p<<<grid, 256, GSMEM>>>(4, 4, 0, Ht, OWt, out, 16384, out_b);
    }
}

// round 16
// speedup vs baseline: 1.0826x; 1.0826x over previous
#include <cuda_runtime.h>
#include <cuda_fp16.h>
#include <math.h>
#include <stdint.h>

#define NN 4096
#define EE 65536

// ------------------- scratch (static device globals; no allocs) -------------
__device__ float g_P[NN * 1024];   // split-K=2 partials (reduced in k_padd)
__device__ float g_A[NN * 256];
__device__ float g_B[NN * 256];
__device__ float g_C[NN * 256];
__device__ float g_D[NN * 128];
__device__ float g_E[NN * 128];
__device__ float g_dinv[NN];
__device__ int   g_rowptr[NN + 1];
__device__ int   g_fill[NN];
__device__ int   g_adj[EE];
// packed fp16 fragment-major operands (stored as uint32 = half2)
__device__ uint32_t g_Xt[NN * NN / 2];
__device__ uint32_t g_Wt[NN * 512 / 2];
__device__ uint32_t g_Ht[NN * 128 / 2];
__device__ uint32_t g_OWt[128 * 16384 / 2];

__device__ __forceinline__ uint32_t pack2h(float a, float b) {
    uint32_t lo = __half_as_ushort(__float2half_rn(a));
    uint32_t hi = __half_as_ushort(__float2half_rn(b));
    return lo | (hi << 16);
}

// --------------------- fused CSR build (1 block, 1024 thr) ------------------
__global__ void k_csr(const int* __restrict__ dst) {
    __shared__ int sc[NN];
    __shared__ int ts[1024];
    int t = threadIdx.x;
    ((int4*)sc)[t] = make_int4(0, 0, 0, 0);
    __syncthreads();
    for (int e = t; e < EE; e += 1024) atomicAdd(&sc[dst[e]], 1);
    __syncthreads();
    int4 c = ((int4*)sc)[t];
    int s = c.x + c.y + c.z + c.w;
    ts[t] = s;
    __syncthreads();
    for (int off = 1; off < 1024; off <<= 1) {
        int x = (t >= off) ? ts[t - off] : 0;
        __syncthreads();
        ts[t] += x;
        __syncthreads();
    }
    int excl = ts[t] - s;
    int p0 = excl, p1 = excl + c.x, p2 = p1 + c.y, p3 = p2 + c.z;
    g_rowptr[4 * t + 0] = p0;  g_fill[4 * t + 0] = p0;
    g_rowptr[4 * t + 1] = p1;  g_fill[4 * t + 1] = p1;
    g_rowptr[4 * t + 2] = p2;  g_fill[4 * t + 2] = p2;
    g_rowptr[4 * t + 3] = p3;  g_fill[4 * t + 3] = p3;
    g_dinv[4 * t + 0] = rsqrtf((float)(c.x + 1));
    g_dinv[4 * t + 1] = rsqrtf((float)(c.y + 1));
    g_dinv[4 * t + 2] = rsqrtf((float)(c.z + 1));
    g_dinv[4 * t + 3] = rsqrtf((float)(c.w + 1));
    if (t == 1023) g_rowptr[NN] = ts[t];
}
__global__ void k_fill(const int* __restrict__ src, const int* __restrict__ dst) {
    int e = blockIdx.x * blockDim.x + threadIdx.x;
    if (e >= EE) return;
    int pos = atomicAdd(&g_fill[dst[e]], 1);
    g_adj[pos] = src[e];
}

// ---- reduce split-K partials: P0 += P1 --------------------------------------
__global__ void k_padd() {
    int i = blockIdx.x * blockDim.x + threadIdx.x;
    if (i >= NN * 128) return;
    float4 a = ((float4*)g_P)[i];
    float4 b = ((const float4*)g_P)[NN * 128 + i];
    a.x += b.x; a.y += b.y; a.z += b.z; a.w += b.w;
    ((float4*)g_P)[i] = a;
}

// ---------------------- gather-based aggregations (unroll x2) ---------------
__global__ void k_sage_gather(const float* __restrict__ bl) {
    int t = blockIdx.x * blockDim.x + threadIdx.x;
    if (t >= NN * 64) return;
    int v = t >> 6;
    int q = t & 63;
    int beg = g_rowptr[v], end = g_rowptr[v + 1];
    const float4* P4 = (const float4*)g_P;
    float4 a0 = make_float4(0.f, 0.f, 0.f, 0.f);
    float4 a1 = make_float4(0.f, 0.f, 0.f, 0.f);
    int i = beg;
    for (; i + 1 < end; i += 2) {
        int s0 = g_adj[i];
        int s1 = g_adj[i + 1];
        float4 p0 = P4[(size_t)s0 * 128 + q];
        float4 p1 = P4[(size_t)s1 * 128 + q];
        a0.x += p0.x; a0.y += p0.y; a0.z += p0.z; a0.w += p0.w;
        a1.x += p1.x; a1.y += p1.y; a1.z += p1.z; a1.w += p1.w;
    }
    if (i < end) {
        int s0 = g_adj[i];
        float4 p0 = P4[(size_t)s0 * 128 + q];
        a0.x += p0.x; a0.y += p0.y; a0.z += p0.z; a0.w += p0.w;
    }
    float4 acc = make_float4(a0.x + a1.x, a0.y + a1.y, a0.z + a1.z, a0.w + a1.w);
    float inv = 1.0f / fmaxf((float)(end - beg), 1.0f);
    float4 b = ((const float4*)bl)[q];
    float4 pr = P4[(size_t)v * 128 + 64 + q];
    float4 r;
    r.x = fmaxf(acc.x * inv + b.x + pr.x, 0.f);
    r.y = fmaxf(acc.y * inv + b.y + pr.y, 0.f);
    r.z = fmaxf(acc.z * inv + b.z + pr.z, 0.f);
    r.w = fmaxf(acc.w * inv + b.w + pr.w, 0.f);
    ((float4*)g_B)[(size_t)v * 64 + q] = r;
}

__global__ void k_gcn_gather(const float* __restrict__ hw, const float* __restrict__ bias,
                             float* __restrict__ out, int hqsh) {
    int t = blockIdx.x * blockDim.x + threadIdx.x;
    if (t >= (NN << hqsh)) return;
    int v = t >> hqsh;
    int q = t & ((1 << hqsh) - 1);
    int Hq = 1 << hqsh;
    int beg = g_rowptr[v], end = g_rowptr[v + 1];
    float dv = g_dinv[v];
    const float4* H4 = (const float4*)hw;
    float4 self = H4[(size_t)v * Hq + q];
    float dv2 = dv * dv;
    float4 a0 = make_float4(dv2 * self.x, dv2 * self.y, dv2 * self.z, dv2 * self.w);
    float4 a1 = make_float4(0.f, 0.f, 0.f, 0.f);
    int i = beg;
    for (; i + 1 < end; i += 2) {
        int s0 = g_adj[i];
        int s1 = g_adj[i + 1];
        float n0 = dv * g_dinv[s0];
        float n1 = dv * g_dinv[s1];
        float4 p0 = H4[(size_t)s0 * Hq + q];
        float4 p1 = H4[(size_t)s1 * Hq + q];
        a0.x += n0 * p0.x; a0.y += n0 * p0.y; a0.z += n0 * p0.z; a0.w += n0 * p0.w;
        a1.x += n1 * p1.x; a1.y += n1 * p1.y; a1.z += n1 * p1.z; a1.w += n1 * p1.w;
    }
    if (i < end) {
        int s0 = g_adj[i];
        float n0 = dv * g_dinv[s0];
        float4 p0 = H4[(size_t)s0 * Hq + q];
        a0.x += n0 * p0.x; a0.y += n0 * p0.y; a0.z += n0 * p0.z; a0.w += n0 * p0.w;
    }
    float4 b = ((const float4*)bias)[q];
    float4 r;
    r.x = fmaxf(a0.x + a1.x + b.x, 0.f);
    r.y = fmaxf(a0.y + a1.y + b.y, 0.f);
    r.z = fmaxf(a0.z + a1.z + b.z, 0.f);
    r.w = fmaxf(a0.w + a1.w + b.w, 0.f);
    ((float4*)out)[(size_t)v * Hq + q] = r;
}

// ---- pack A to fp16 fragment-major (m16n8k16), flat (R13 version) ----------
__global__ void k_packAh(const float* __restrict__ in, uint32_t* __restrict__ out,
                         int K, int lda) {
    int o = blockIdx.x * blockDim.x + threadIdx.x;
    int ktp = K >> 5;
    int perBlk = ktp << 11;
    int br = o / perBlk;
    int r = o - br * perBlk;
    int kt = r >> 11;
    int q = r & 2047;
    int reg = q & 3;
    int lane = (q >> 2) & 31;
    int t8 = (q >> 7) & 7;
    int s = q >> 10;
    int qm = lane >> 2;
    int qk = lane & 3;
    int m = br * 128 + t8 * 16 + qm + (reg & 1) * 8;
    int k = kt * 32 + s * 16 + 2 * qk + (reg & 2) * 4;
    float2 v = *(const float2*)&in[(size_t)m * lda + k];
    out[o] = pack2h(v.x, v.y);
}

// ---- pack B to fp16 fragment-major, PAIRED n-fragments (BN=128) ------------
__global__ void k_packBh(const float* __restrict__ B0, const float* __restrict__ B1,
                         int nsplit, int K, int ldb, uint32_t* __restrict__ out) {
    int o = blockIdx.x * blockDim.x + threadIdx.x;
    int ktp = K >> 5;
    int perBc = ktp << 11;
    int bc = o / perBc;
    int r = o - bc * perBc;
    int kt = r >> 11;
    int q = r & 2047;
    int reg = q & 3;
    int lane = (q >> 2) & 31;
    int u2 = (q >> 7) & 7;
    int s = q >> 10;
    int qm = lane >> 2;
    int qk = lane & 3;
    int n = bc * 128 + u2 * 16 + qm + ((reg >> 1) & 1) * 8;
    int k = kt * 32 + s * 16 + 2 * qk + (reg & 1) * 8;
    const float* src = B0;
    if (n >= nsplit) { src = B1; n -= nsplit; }
    float v0 = src[(size_t)k * ldb + n];
    float v1 = src[(size_t)(k + 1) * ldb + n];
    out[o] = pack2h(v0, v1);
}

// ------------------- fp32 SIMT GEMM, 64x64x16 tiles (GCN layers) ------------
__global__ void __launch_bounds__(256, 4)
sgemm64(int M, int N, int K,
        const float* __restrict__ A, int lda,
        const float* __restrict__ B, int ldb,
        float* __restrict__ C, int ldc)
{
    const int BK = 16;
    __shared__ float As[2][BK][64];
    __shared__ float Bs[2][BK][64];

    int tid = threadIdx.x;
    int tx = tid & 15;
    int ty = tid >> 4;
    int row0 = blockIdx.y * 64;
    int col0 = blockIdx.x * 64;

    int am = tid >> 2;
    int ak = (tid & 3) << 2;
    int bk = tid >> 4;
    int bn = (tid & 15) << 2;

    const float* Aptr = A + (size_t)(row0 + am) * lda + ak;
    const float* Bptr = B + (size_t)bk * ldb + col0 + bn;
    size_t bstep = (size_t)BK * ldb;

    float4 av = *(const float4*)Aptr;
    float4 bv = *(const float4*)Bptr;
    As[0][ak + 0][am] = av.x;
    As[0][ak + 1][am] = av.y;
    As[0][ak + 2][am] = av.z;
    As[0][ak + 3][am] = av.w;
    *(float4*)&Bs[0][bk][bn] = bv;
    __syncthreads();

    float acc[4][4];
    #pragma unroll
    for (int i = 0; i < 4; i++)
        #pragma unroll
        for (int j = 0; j < 4; j++) acc[i][j] = 0.0f;

    int ntiles = K / BK;
    for (int t = 0; t < ntiles; t++) {
        int buf = t & 1;
        if (t + 1 < ntiles) {
            av = *(const float4*)(Aptr + (size_t)(t + 1) * BK);
            bv = *(const float4*)(Bptr + (size_t)(t + 1) * bstep);
        }
        #pragma unroll
        for (int k = 0; k < BK; k++) {
            float a[4], b[4];
            *(float4*)&a[0] = *(float4*)&As[buf][k][ty * 4];
            *(float4*)&b[0] = *(float4*)&Bs[buf][k][tx * 4];
            #pragma unroll
            for (int i = 0; i < 4; i++)
                #pragma unroll
                for (int j = 0; j < 4; j++)
                    acc[i][j] = fmaf(a[i], b[j], acc[i][j]);
        }
        if (t + 1 < ntiles) {
            int nb = buf ^ 1;
            As[nb][ak + 0][am] = av.x;
            As[nb][ak + 1][am] = av.y;
            As[nb][ak + 2][am] = av.z;
            As[nb][ak + 3][am] = av.w;
            *(float4*)&Bs[nb][bk][bn] = bv;
            __syncthreads();
        }
    }

    #pragma unroll
    for (int i = 0; i < 4; i++) {
        int gm = row0 + ty * 4 + i;
        int gn = col0 + tx * 4;
        *(float4*)&C[(size_t)gm * ldc + gn] =
            make_float4(acc[i][0], acc[i][1], acc[i][2], acc[i][3]);
    }
}

// ---------------- fused fc1+fc2: C = relu(relu(D@W1+b1)@W2+b2) --------------
__global__ void __launch_bounds__(256, 2)
k_fc12(const float* __restrict__ D,
       const float* __restrict__ W1, const float* __restrict__ b1,
       const float* __restrict__ W2, const float* __restrict__ b2,
       float* __restrict__ C)
{
    __shared__ float As[16][64];
    __shared__ float Bs[16][128];
    __shared__ float hs[64][132];

    int tid = threadIdx.x;
    int tx = tid & 15;
    int ty = tid >> 4;
    int row0 = blockIdx.x * 64;
    int am = tid >> 2;
    int ak = (tid & 3) << 2;

    float acc[4][8];
    #pragma unroll
    for (int i = 0; i < 4; i++)
        #pragma unroll
        for (int j = 0; j < 8; j++) acc[i][j] = 0.0f;

    for (int t = 0; t < 8; t++) {
        __syncthreads();
        {
            float4 av = *(const float4*)&D[(size_t)(row0 + am) * 128 + t * 16 + ak];
            As[ak + 0][am] = av.x;
            As[ak + 1][am] = av.y;
            As[ak + 2][am] = av.z;
            As[ak + 3][am] = av.w;
            #pragma unroll
            for (int l = 0; l < 2; l++) {
                int i = tid + l * 256;
                int bk = i >> 5;
                int bn = (i & 31) << 2;
                *(float4*)&Bs[bk][bn] = *(const float4*)&W1[(size_t)(t * 16 + bk) * 128 + bn];
            }
        }
        __syncthreads();
        #pragma unroll
        for (int k = 0; k < 16; k++) {
            float a[4], b[8];
            *(float4*)&a[0] = *(float4*)&As[k][ty * 4];
            *(float4*)&b[0] = *(float4*)&Bs[k][tx * 8];
            *(float4*)&b[4] = *(float4*)&Bs[k][tx * 8 + 4];
            #pragma unroll
            for (int i = 0; i < 4; i++)
                #pragma unroll
                for (int j = 0; j < 8; j++)
                    acc[i][j] = fmaf(a[i], b[j], acc[i][j]);
        }
    }
    __syncthreads();
    #pragma unroll
    for (int i = 0; i < 4; i++)
        #pragma unroll
        for (int j = 0; j < 8; j++)
            hs[ty * 4 + i][tx * 8 + j] = fmaxf(acc[i][j] + b1[tx * 8 + j], 0.0f);

    #pragma unroll
    for (int i = 0; i < 4; i++)
        #pragma unroll
        for (int j = 0; j < 8; j++) acc[i][j] = 0.0f;

    for (int t = 0; t < 8; t++) {
        __syncthreads();
        #pragma unroll
        for (int l = 0; l < 2; l++) {
            int i = tid + l * 256;
            int bk = i >> 5;
            int bn = (i & 31) << 2;
            *(float4*)&Bs[bk][bn] = *(const float4*)&W2[(size_t)(t * 16 + bk) * 128 + bn];
        }
        __syncthreads();
        #pragma unroll
        for (int k = 0; k < 16; k++) {
            int kk = t * 16 + k;
            float b[8];
            *(float4*)&b[0] = *(float4*)&Bs[k][tx * 8];
            *(float4*)&b[4] = *(float4*)&Bs[k][tx * 8 + 4];
            #pragma unroll
            for (int i = 0; i < 4; i++) {
                float a = hs[ty * 4 + i][kk];
                #pragma unroll
                for (int j = 0; j < 8; j++)
                    acc[i][j] = fmaf(a, b[j], acc[i][j]);
            }
        }
    }
    #pragma unroll
    for (int i = 0; i < 4; i++) {
        int gm = row0 + ty * 4 + i;
        #pragma unroll
        for (int j = 0; j < 8; j += 4) {
            int gn = tx * 8 + j;
            float4 v;
            v.x = fmaxf(acc[i][j + 0] + b2[gn + 0], 0.f);
            v.y = fmaxf(acc[i][j + 1] + b2[gn + 1], 0.f);
            v.z = fmaxf(acc[i][j + 2] + b2[gn + 2], 0.f);
            v.w = fmaxf(acc[i][j + 3] + b2[gn + 3], 0.f);
            *(float4*)&C[(size_t)gm * 128 + gn] = v;
        }
    }
}

// ------------- fp16 mma.sync GEMM (m16n8k16), cp.async 4-stage ---------------
__device__ __forceinline__ void mma_f16(float* c, const uint32_t* a, const uint32_t* b) {
    asm volatile(
        "mma.sync.aligned.m16n8k16.row.col.f32.f16.f16.f32 "
        "{%0,%1,%2,%3}, {%4,%5,%6,%7}, {%8,%9}, {%0,%1,%2,%3};"
        : "+f"(c[0]), "+f"(c[1]), "+f"(c[2]), "+f"(c[3])
        : "r"(a[0]), "r"(a[1]), "r"(a[2]), "r"(a[3]), "r"(b[0]), "r"(b[1]));
}
__device__ __forceinline__ void cp16(uint32_t s, const void* g) {
    asm volatile("cp.async.cg.shared.global [%0], [%1], 16;" :: "r"(s), "l"(g));
}

__global__ void __launch_bounds__(256, 2)
gemm_fp16p(int ktiles, int ktstride, size_t czstride,
           const uint32_t* __restrict__ At,
           const uint32_t* __restrict__ Bt,
           float* __restrict__ C, int ldc,
           const float* __restrict__ bias)
{
    const int MFRAG = 4;
    const int NFRAG = 4;
    const int TILE = 2048;

    extern __shared__ __align__(16) uint32_t smem[];
    uint32_t* AsF = smem;
    uint32_t* BsF = smem + 4 * TILE;

    int tid = threadIdx.x;
    int lane = tid & 31;
    int warp = tid >> 5;
    int warp_m = warp >> 2;
    int warp_n = warp & 3;

    int br = blockIdx.y;
    int bc = blockIdx.x;
    int kt0 = blockIdx.z * ktiles;

    const uint4* Ab = (const uint4*)At + ((size_t)br * ktstride + kt0) * (TILE / 4);
    const uint4* Bb = (const uint4*)Bt + ((size_t)bc * ktstride + kt0) * (TILE / 4);
    C += (size_t)blockIdx.z * czstride;

    uint32_t sbase = (uint32_t)__cvta_generic_to_shared(smem);
    uint32_t sb_b = sbase + 4 * TILE * 4;

    auto issue = [&](int t) {
        int slot = t & 3;
        const uint4* An = Ab + (size_t)t * (TILE / 4);
        const uint4* Bn = Bb + (size_t)t * (TILE / 4);
        uint32_t a0 = sbase + slot * (TILE * 4) + tid * 16;
        cp16(a0, An + tid);
        cp16(a0 + 4096, An + tid + 256);
        uint32_t b0 = sb_b + slot * (TILE * 4) + tid * 16;
        cp16(b0, Bn + tid);
        cp16(b0 + 4096, Bn + tid + 256);
        asm volatile("cp.async.commit_group;" ::: "memory");
    };

    issue(0);
    if (ktiles > 1) issue(1);
    if (ktiles > 2) issue(2);

    float acc[MFRAG][NFRAG][4];
    #pragma unroll
    for (int mi = 0; mi < MFRAG; mi++)
        #pragma unroll
        for (int ni = 0; ni < NFRAG; ni++)
            #pragma unroll
            for (int j = 0; j < 4; j++) acc[mi][ni][j] = 0.0f;

    for (int t = 0; t < ktiles; t++) {
        int rem = ktiles - 1 - t;
        if (rem >= 2)      asm volatile("cp.async.wait_group 2;" ::: "memory");
        else if (rem == 1) asm volatile("cp.async.wait_group 1;" ::: "memory");
        else               asm volatile("cp.async.wait_group 0;" ::: "memory");
        __syncthreads();

        if (t + 3 < ktiles) issue(t + 3);

        int slot = t & 3;
        const uint32_t* As = AsF + slot * TILE;
        const uint32_t* Bs = BsF + slot * TILE;

        #pragma unroll
        for (int s = 0; s < 2; s++) {
            uint32_t afr[MFRAG][4];
            uint32_t bfr[NFRAG][2];
            #pragma unroll
            for (int mi = 0; mi < MFRAG; mi++) {
                int t8 = warp_m * MFRAG + mi;
                uint4 fa = *(const uint4*)&As[(((s << 3) + t8) * 32 + lane) * 4];
                afr[mi][0] = fa.x; afr[mi][1] = fa.y;
                afr[mi][2] = fa.z; afr[mi][3] = fa.w;
            }
            #pragma unroll
            for (int ni2 = 0; ni2 < NFRAG / 2; ni2++) {
                int u2 = warp_n * (NFRAG / 2) + ni2;
                uint4 fb = *(const uint4*)&Bs[(((s << 3) + u2) * 32 + lane) * 4];
                bfr[2 * ni2][0]     = fb.x;
                bfr[2 * ni2][1]     = fb.y;
                bfr[2 * ni2 + 1][0] = fb.z;
                bfr[2 * ni2 + 1][1] = fb.w;
            }
            #pragma unroll
            for (int mi = 0; mi < MFRAG; mi++)
                #pragma unroll
                for (int ni = 0; ni < NFRAG; ni++)
                    mma_f16(acc[mi][ni], afr[mi], bfr[ni]);
        }
    }

    int qm = lane >> 2;
    int qk = lane & 3;
    #pragma unroll
    for (int mi = 0; mi < MFRAG; mi++) {
        int r = br * 128 + warp_m * 64 + mi * 16 + qm;
        #pragma unroll
        for (int ni = 0; ni < NFRAG; ni++) {
            int c = bc * 128 + warp_n * 32 + ni * 8 + 2 * qk;
            float2 v0 = make_float2(acc[mi][ni][0], acc[mi][ni][1]);
            float2 v1 = make_float2(acc[mi][ni][2], acc[mi][ni][3]);
            if (bias) {
                float2 bb = *(const float2*)&bias[c];
                v0.x += bb.x; v0.y += bb.y;
                v1.x += bb.x; v1.y += bb.y;
            }
            *(float2*)&C[(size_t)r * ldc + c] = v0;
            *(float2*)&C[(size_t)(r + 8) * ldc + c] = v1;
        }
    }
}

// ------------------------------ host orchestration ---------------------------
extern "C" void kernel_launch(void* const* d_in, const int* in_sizes, int n_in,
                              void* d_out, int out_size)
{
    const float* x       = (const float*)d_in[0];
    const int*   eidx    = (const int*)  d_in[1];
    const float* sage_Wl = (const float*)d_in[2];
    const float* sage_bl = (const float*)d_in[3];
    const float* sage_Wr = (const float*)d_in[4];
    const float* gcn1_W  = (const float*)d_in[5];
    const float* gcn1_b  = (const float*)d_in[6];
    const float* gcn2_W  = (const float*)d_in[7];
    const float* gcn2_b  = (const float*)d_in[8];
    const float* fc1_W   = (const float*)d_in[9];
    const float* fc1_b   = (const float*)d_in[10];
    const float* fc2_W   = (const float*)d_in[11];
    const float* fc2_b   = (const float*)d_in[12];
    const float* out_W   = (const float*)d_in[13];
    const float* out_b   = (const float*)d_in[14];
    float* out = (float*)d_out;

    const int* src = eidx;
    const int* dst = eidx + EE;

    float *P, *A, *B, *C, *D, *E;
    uint32_t *Xt, *Wt, *Ht, *OWt;
    cudaGetSymbolAddress((void**)&P, g_P);
    cudaGetSymbolAddress((void**)&A, g_A);
    cudaGetSymbolAddress((void**)&B, g_B);
    cudaGetSymbolAddress((void**)&C, g_C);
    cudaGetSymbolAddress((void**)&D, g_D);
    cudaGetSymbolAddress((void**)&E, g_E);
    cudaGetSymbolAddress((void**)&Xt, g_Xt);
    cudaGetSymbolAddress((void**)&Wt, g_Wt);
    cudaGetSymbolAddress((void**)&Ht, g_Ht);
    cudaGetSymbolAddress((void**)&OWt, g_OWt);

    const int TPB = 256;
    const int GSMEM = 8 * 2048 * 4;   // 64KB: 4-slot A+B ring
    cudaFuncSetAttribute(gemm_fp16p, cudaFuncAttributeMaxDynamicSharedMemorySize, GSMEM);

    // CSR build (R13 structure: scan kernel + separate fill)
    k_csr<<<1, 1024>>>(dst);
    k_fill<<<(EE + TPB - 1) / TPB, TPB>>>(src, dst);

    // pack operands (fp16 fragment-major, flat packs)
    k_packAh<<<NN * NN / 2 / TPB, TPB>>>(x, Xt, NN, NN);
    k_packBh<<<NN * 512 / 2 / TPB, TPB>>>(sage_Wl, sage_Wr, 256, NN, 256, Wt);
    k_packBh<<<128 * 16384 / 2 / TPB, TPB>>>(out_W, out_W, 16384, 128, 16384, OWt);

    // P = x @ [Wl | Wr], split-K=2: grid (4,32,2), 64 k-tiles of 32 each
    {
        dim3 grid(512 / 128, NN / 128, 2);
        gemm_fp16p<<<grid, 256, GSMEM>>>(64, 128, (size_t)NN * 512, Xt, Wt, P, 512, nullptr);
    }
    k_padd<<<NN * 128 / TPB, TPB>>>();

    // SAGE (gather, fused combine) -> B
    k_sage_gather<<<NN * 64 / TPB, TPB>>>(sage_bl);

    // GCN1: hw -> C, gather+bias+relu -> A
    {
        dim3 grid(256 / 64, NN / 64);
        sgemm64<<<grid, 256>>>(NN, 256, 256, B, 256, gcn1_W, 256, C, 256);
    }
    k_gcn_gather<<<NN * 64 / TPB, TPB>>>(C, gcn1_b, A, 6);

    // GCN2: hw -> D, gather+bias+relu -> E
    {
        dim3 grid(128 / 64, NN / 64);
        sgemm64<<<grid, 256>>>(NN, 128, 256, A, 256, gcn2_W, 128, D, 128);
    }
    k_gcn_gather<<<NN * 32 / TPB, TPB>>>(D, gcn2_b, E, 5);

    // fused fc1+fc2: E -> C
    k_fc12<<<NN / 64, 256>>>(E, fc1_W, fc1_b, fc2_W, fc2_b, C);

    // head GEMM (4096 x 16384 x 128): 4 k-tiles
    k_packAh<<<NN * 128 / 2 / TPB, TPB>>>(C, Ht, 128, 128);
    {
        dim3 grid(16384 / 128, NN / 128, 1);
        gemm_fp16p<<<grid, 256, GSMEM>>>(4, 4, 0, Ht, OWt, out, 16384, out_b);
    }
}

// round 17
// speedup vs baseline: 1.1471x; 1.0596x over previous
#include <cuda_runtime.h>
#include <cuda_fp16.h>
#include <math.h>
#include <stdint.h>

#define NN 4096
#define EE 65536

// ------------------- scratch (static device globals; no allocs) -------------
__device__ float g_P[NN * 1024];   // split-K=2 partials (reduced in k_padd)
__device__ float g_A[NN * 256];
__device__ float g_B[NN * 256];
__device__ float g_C[NN * 256];
__device__ float g_D[NN * 128];
__device__ float g_E[NN * 128];
__device__ float g_dinv[NN];
__device__ int   g_rowptr[NN + 1];
__device__ int   g_fill[NN];
__device__ int   g_adj[EE];
// packed fp16 fragment-major operands (stored as uint32 = half2)
__device__ uint32_t g_Xt[NN * NN / 2];
__device__ uint32_t g_Wt[NN * 512 / 2];
__device__ uint32_t g_Ht[NN * 128 / 2];
__device__ uint32_t g_OWt[128 * 16384 / 2];

__device__ __forceinline__ uint32_t pack2h(float a, float b) {
    uint32_t lo = __half_as_ushort(__float2half_rn(a));
    uint32_t hi = __half_as_ushort(__float2half_rn(b));
    return lo | (hi << 16);
}

// --------------------- fused CSR build (1 block, 1024 thr) ------------------
__global__ void k_csr(const int* __restrict__ dst) {
    __shared__ int sc[NN];
    __shared__ int ts[1024];
    int t = threadIdx.x;
    ((int4*)sc)[t] = make_int4(0, 0, 0, 0);
    __syncthreads();
    for (int e = t; e < EE; e += 1024) atomicAdd(&sc[dst[e]], 1);
    __syncthreads();
    int4 c = ((int4*)sc)[t];
    int s = c.x + c.y + c.z + c.w;
    ts[t] = s;
    __syncthreads();
    for (int off = 1; off < 1024; off <<= 1) {
        int x = (t >= off) ? ts[t - off] : 0;
        __syncthreads();
        ts[t] += x;
        __syncthreads();
    }
    int excl = ts[t] - s;
    int p0 = excl, p1 = excl + c.x, p2 = p1 + c.y, p3 = p2 + c.z;
    g_rowptr[4 * t + 0] = p0;  g_fill[4 * t + 0] = p0;
    g_rowptr[4 * t + 1] = p1;  g_fill[4 * t + 1] = p1;
    g_rowptr[4 * t + 2] = p2;  g_fill[4 * t + 2] = p2;
    g_rowptr[4 * t + 3] = p3;  g_fill[4 * t + 3] = p3;
    g_dinv[4 * t + 0] = rsqrtf((float)(c.x + 1));
    g_dinv[4 * t + 1] = rsqrtf((float)(c.y + 1));
    g_dinv[4 * t + 2] = rsqrtf((float)(c.z + 1));
    g_dinv[4 * t + 3] = rsqrtf((float)(c.w + 1));
    if (t == 1023) g_rowptr[NN] = ts[t];
}
__global__ void k_fill(const int* __restrict__ src, const int* __restrict__ dst) {
    int e = blockIdx.x * blockDim.x + threadIdx.x;
    if (e >= EE) return;
    int pos = atomicAdd(&g_fill[dst[e]], 1);
    g_adj[pos] = src[e];
}

// ---- reduce split-K partials: P0 += P1 --------------------------------------
__global__ void k_padd() {
    int i = blockIdx.x * blockDim.x + threadIdx.x;
    if (i >= NN * 128) return;
    float4 a = ((float4*)g_P)[i];
    float4 b = ((const float4*)g_P)[NN * 128 + i];
    a.x += b.x; a.y += b.y; a.z += b.z; a.w += b.w;
    ((float4*)g_P)[i] = a;
}

// ---------------------- gather-based aggregations (unroll x2) ---------------
__global__ void k_sage_gather(const float* __restrict__ bl) {
    int t = blockIdx.x * blockDim.x + threadIdx.x;
    if (t >= NN * 64) return;
    int v = t >> 6;
    int q = t & 63;
    int beg = g_rowptr[v], end = g_rowptr[v + 1];
    const float4* P4 = (const float4*)g_P;
    float4 a0 = make_float4(0.f, 0.f, 0.f, 0.f);
    float4 a1 = make_float4(0.f, 0.f, 0.f, 0.f);
    int i = beg;
    for (; i + 1 < end; i += 2) {
        int s0 = g_adj[i];
        int s1 = g_adj[i + 1];
        float4 p0 = P4[(size_t)s0 * 128 + q];
        float4 p1 = P4[(size_t)s1 * 128 + q];
        a0.x += p0.x; a0.y += p0.y; a0.z += p0.z; a0.w += p0.w;
        a1.x += p1.x; a1.y += p1.y; a1.z += p1.z; a1.w += p1.w;
    }
    if (i < end) {
        int s0 = g_adj[i];
        float4 p0 = P4[(size_t)s0 * 128 + q];
        a0.x += p0.x; a0.y += p0.y; a0.z += p0.z; a0.w += p0.w;
    }
    float4 acc = make_float4(a0.x + a1.x, a0.y + a1.y, a0.z + a1.z, a0.w + a1.w);
    float inv = 1.0f / fmaxf((float)(end - beg), 1.0f);
    float4 b = ((const float4*)bl)[q];
    float4 pr = P4[(size_t)v * 128 + 64 + q];
    float4 r;
    r.x = fmaxf(acc.x * inv + b.x + pr.x, 0.f);
    r.y = fmaxf(acc.y * inv + b.y + pr.y, 0.f);
    r.z = fmaxf(acc.z * inv + b.z + pr.z, 0.f);
    r.w = fmaxf(acc.w * inv + b.w + pr.w, 0.f);
    ((float4*)g_B)[(size_t)v * 64 + q] = r;
}

__global__ void k_gcn_gather(const float* __restrict__ hw, const float* __restrict__ bias,
                             float* __restrict__ out, int hqsh) {
    int t = blockIdx.x * blockDim.x + threadIdx.x;
    if (t >= (NN << hqsh)) return;
    int v = t >> hqsh;
    int q = t & ((1 << hqsh) - 1);
    int Hq = 1 << hqsh;
    int beg = g_rowptr[v], end = g_rowptr[v + 1];
    float dv = g_dinv[v];
    const float4* H4 = (const float4*)hw;
    float4 self = H4[(size_t)v * Hq + q];
    float dv2 = dv * dv;
    float4 a0 = make_float4(dv2 * self.x, dv2 * self.y, dv2 * self.z, dv2 * self.w);
    float4 a1 = make_float4(0.f, 0.f, 0.f, 0.f);
    int i = beg;
    for (; i + 1 < end; i += 2) {
        int s0 = g_adj[i];
        int s1 = g_adj[i + 1];
        float n0 = dv * g_dinv[s0];
        float n1 = dv * g_dinv[s1];
        float4 p0 = H4[(size_t)s0 * Hq + q];
        float4 p1 = H4[(size_t)s1 * Hq + q];
        a0.x += n0 * p0.x; a0.y += n0 * p0.y; a0.z += n0 * p0.z; a0.w += n0 * p0.w;
        a1.x += n1 * p1.x; a1.y += n1 * p1.y; a1.z += n1 * p1.z; a1.w += n1 * p1.w;
    }
    if (i < end) {
        int s0 = g_adj[i];
        float n0 = dv * g_dinv[s0];
        float4 p0 = H4[(size_t)s0 * Hq + q];
        a0.x += n0 * p0.x; a0.y += n0 * p0.y; a0.z += n0 * p0.z; a0.w += n0 * p0.w;
    }
    float4 b = ((const float4*)bias)[q];
    float4 r;
    r.x = fmaxf(a0.x + a1.x + b.x, 0.f);
    r.y = fmaxf(a0.y + a1.y + b.y, 0.f);
    r.z = fmaxf(a0.z + a1.z + b.z, 0.f);
    r.w = fmaxf(a0.w + a1.w + b.w, 0.f);
    ((float4*)out)[(size_t)v * Hq + q] = r;
}

// ---- pack A to fp16 fragment-major, smem-staged, coalesced loads -----------
// One block per (128-row, 32-k) tile. Load: 8 threads/row x float4 = 128B/row
// fully coalesced; 4 rows per warp per iteration. Store: linear u32 stream.
// Output layout per tile: index q -> reg=q&3, lane=(q>>2)&31, t8=(q>>7)&7,
// s=q>>10; qm=lane>>2, qk=lane&3;
//   m_local = t8*16 + qm + (reg&1)*8, k_local = s*16 + 2*qk + (reg&2)*4.
__global__ void __launch_bounds__(256)
k_packAh(const float* __restrict__ in, uint32_t* __restrict__ out, int lda) {
    __shared__ float st[128][33];
    int b = blockIdx.x;
    int ktp = lda >> 5;
    int br = b / ktp;
    int kt = b - br * ktp;
    int tid = threadIdx.x;

    // coalesced load: thread covers one float4; 8 threads span a 128B row
    int row = tid >> 3;          // 0..31 (x4 iterations -> 128 rows)
    int c4  = (tid & 7) << 2;    // float offset 0,4,...,28
    #pragma unroll
    for (int l = 0; l < 4; l++) {
        int r = row + l * 32;
        float4 v = *(const float4*)&in[(size_t)(br * 128 + r) * lda + kt * 32 + c4];
        st[r][c4 + 0] = v.x;
        st[r][c4 + 1] = v.y;
        st[r][c4 + 2] = v.z;
        st[r][c4 + 3] = v.w;
    }
    __syncthreads();

    uint32_t* outp = out + (size_t)b * 2048;
    #pragma unroll
    for (int i = 0; i < 8; i++) {
        int o = tid + i * 256;
        int reg = o & 3;
        int lane = (o >> 2) & 31;
        int t8 = (o >> 7) & 7;
        int s = o >> 10;
        int qm = lane >> 2;
        int qk = lane & 3;
        int ml = t8 * 16 + qm + (reg & 1) * 8;
        int kl = s * 16 + 2 * qk + (reg & 2) * 4;
        outp[o] = pack2h(st[ml][kl], st[ml][kl + 1]);
    }
}

// ---- pack B to fp16 fragment-major, PAIRED n-fragments (BN=128) ------------
__global__ void k_packBh(const float* __restrict__ B0, const float* __restrict__ B1,
                         int nsplit, int K, int ldb, uint32_t* __restrict__ out) {
    int o = blockIdx.x * blockDim.x + threadIdx.x;
    int ktp = K >> 5;
    int perBc = ktp << 11;
    int bc = o / perBc;
    int r = o - bc * perBc;
    int kt = r >> 11;
    int q = r & 2047;
    int reg = q & 3;
    int lane = (q >> 2) & 31;
    int u2 = (q >> 7) & 7;
    int s = q >> 10;
    int qm = lane >> 2;
    int qk = lane & 3;
    int n = bc * 128 + u2 * 16 + qm + ((reg >> 1) & 1) * 8;
    int k = kt * 32 + s * 16 + 2 * qk + (reg & 1) * 8;
    const float* src = B0;
    if (n >= nsplit) { src = B1; n -= nsplit; }
    float v0 = src[(size_t)k * ldb + n];
    float v1 = src[(size_t)(k + 1) * ldb + n];
    out[o] = pack2h(v0, v1);
}

// ------------------- fp32 SIMT GEMM, 64x64x16 tiles (GCN layers) ------------
__global__ void __launch_bounds__(256, 4)
sgemm64(int M, int N, int K,
        const float* __restrict__ A, int lda,
        const float* __restrict__ B, int ldb,
        float* __restrict__ C, int ldc)
{
    const int BK = 16;
    __shared__ float As[2][BK][64];
    __shared__ float Bs[2][BK][64];

    int tid = threadIdx.x;
    int tx = tid & 15;
    int ty = tid >> 4;
    int row0 = blockIdx.y * 64;
    int col0 = blockIdx.x * 64;

    int am = tid >> 2;
    int ak = (tid & 3) << 2;
    int bk = tid >> 4;
    int bn = (tid & 15) << 2;

    const float* Aptr = A + (size_t)(row0 + am) * lda + ak;
    const float* Bptr = B + (size_t)bk * ldb + col0 + bn;
    size_t bstep = (size_t)BK * ldb;

    float4 av = *(const float4*)Aptr;
    float4 bv = *(const float4*)Bptr;
    As[0][ak + 0][am] = av.x;
    As[0][ak + 1][am] = av.y;
    As[0][ak + 2][am] = av.z;
    As[0][ak + 3][am] = av.w;
    *(float4*)&Bs[0][bk][bn] = bv;
    __syncthreads();

    float acc[4][4];
    #pragma unroll
    for (int i = 0; i < 4; i++)
        #pragma unroll
        for (int j = 0; j < 4; j++) acc[i][j] = 0.0f;

    int ntiles = K / BK;
    for (int t = 0; t < ntiles; t++) {
        int buf = t & 1;
        if (t + 1 < ntiles) {
            av = *(const float4*)(Aptr + (size_t)(t + 1) * BK);
            bv = *(const float4*)(Bptr + (size_t)(t + 1) * bstep);
        }
        #pragma unroll
        for (int k = 0; k < BK; k++) {
            float a[4], b[4];
            *(float4*)&a[0] = *(float4*)&As[buf][k][ty * 4];
            *(float4*)&b[0] = *(float4*)&Bs[buf][k][tx * 4];
            #pragma unroll
            for (int i = 0; i < 4; i++)
                #pragma unroll
                for (int j = 0; j < 4; j++)
                    acc[i][j] = fmaf(a[i], b[j], acc[i][j]);
        }
        if (t + 1 < ntiles) {
            int nb = buf ^ 1;
            As[nb][ak + 0][am] = av.x;
            As[nb][ak + 1][am] = av.y;
            As[nb][ak + 2][am] = av.z;
            As[nb][ak + 3][am] = av.w;
            *(float4*)&Bs[nb][bk][bn] = bv;
            __syncthreads();
        }
    }

    #pragma unroll
    for (int i = 0; i < 4; i++) {
        int gm = row0 + ty * 4 + i;
        int gn = col0 + tx * 4;
        *(float4*)&C[(size_t)gm * ldc + gn] =
            make_float4(acc[i][0], acc[i][1], acc[i][2], acc[i][3]);
    }
}

// ---------------- fused fc1+fc2: C = relu(relu(D@W1+b1)@W2+b2) --------------
__global__ void __launch_bounds__(256, 2)
k_fc12(const float* __restrict__ D,
       const float* __restrict__ W1, const float* __restrict__ b1,
       const float* __restrict__ W2, const float* __restrict__ b2,
       float* __restrict__ C)
{
    __shared__ float As[16][64];
    __shared__ float Bs[16][128];
    __shared__ float hs[64][132];

    int tid = threadIdx.x;
    int tx = tid & 15;
    int ty = tid >> 4;
    int row0 = blockIdx.x * 64;
    int am = tid >> 2;
    int ak = (tid & 3) << 2;

    float acc[4][8];
    #pragma unroll
    for (int i = 0; i < 4; i++)
        #pragma unroll
        for (int j = 0; j < 8; j++) acc[i][j] = 0.0f;

    for (int t = 0; t < 8; t++) {
        __syncthreads();
        {
            float4 av = *(const float4*)&D[(size_t)(row0 + am) * 128 + t * 16 + ak];
            As[ak + 0][am] = av.x;
            As[ak + 1][am] = av.y;
            As[ak + 2][am] = av.z;
            As[ak + 3][am] = av.w;
            #pragma unroll
            for (int l = 0; l < 2; l++) {
                int i = tid + l * 256;
                int bk = i >> 5;
                int bn = (i & 31) << 2;
                *(float4*)&Bs[bk][bn] = *(const float4*)&W1[(size_t)(t * 16 + bk) * 128 + bn];
            }
        }
        __syncthreads();
        #pragma unroll
        for (int k = 0; k < 16; k++) {
            float a[4], b[8];
            *(float4*)&a[0] = *(float4*)&As[k][ty * 4];
            *(float4*)&b[0] = *(float4*)&Bs[k][tx * 8];
            *(float4*)&b[4] = *(float4*)&Bs[k][tx * 8 + 4];
            #pragma unroll
            for (int i = 0; i < 4; i++)
                #pragma unroll
                for (int j = 0; j < 8; j++)
                    acc[i][j] = fmaf(a[i], b[j], acc[i][j]);
        }
    }
    __syncthreads();
    #pragma unroll
    for (int i = 0; i < 4; i++)
        #pragma unroll
        for (int j = 0; j < 8; j++)
            hs[ty * 4 + i][tx * 8 + j] = fmaxf(acc[i][j] + b1[tx * 8 + j], 0.0f);

    #pragma unroll
    for (int i = 0; i < 4; i++)
        #pragma unroll
        for (int j = 0; j < 8; j++) acc[i][j] = 0.0f;

    for (int t = 0; t < 8; t++) {
        __syncthreads();
        #pragma unroll
        for (int l = 0; l < 2; l++) {
            int i = tid + l * 256;
            int bk = i >> 5;
            int bn = (i & 31) << 2;
            *(float4*)&Bs[bk][bn] = *(const float4*)&W2[(size_t)(t * 16 + bk) * 128 + bn];
        }
        __syncthreads();
        #pragma unroll
        for (int k = 0; k < 16; k++) {
            int kk = t * 16 + k;
            float b[8];
            *(float4*)&b[0] = *(float4*)&Bs[k][tx * 8];
            *(float4*)&b[4] = *(float4*)&Bs[k][tx * 8 + 4];
            #pragma unroll
            for (int i = 0; i < 4; i++) {
                float a = hs[ty * 4 + i][kk];
                #pragma unroll
                for (int j = 0; j < 8; j++)
                    acc[i][j] = fmaf(a, b[j], acc[i][j]);
            }
        }
    }
    #pragma unroll
    for (int i = 0; i < 4; i++) {
        int gm = row0 + ty * 4 + i;
        #pragma unroll
        for (int j = 0; j < 8; j += 4) {
            int gn = tx * 8 + j;
            float4 v;
            v.x = fmaxf(acc[i][j + 0] + b2[gn + 0], 0.f);
            v.y = fmaxf(acc[i][j + 1] + b2[gn + 1], 0.f);
            v.z = fmaxf(acc[i][j + 2] + b2[gn + 2], 0.f);
            v.w = fmaxf(acc[i][j + 3] + b2[gn + 3], 0.f);
            *(float4*)&C[(size_t)gm * 128 + gn] = v;
        }
    }
}

// ------------- fp16 mma.sync GEMM (m16n8k16), cp.async 4-stage ---------------
__device__ __forceinline__ void mma_f16(float* c, const uint32_t* a, const uint32_t* b) {
    asm volatile(
        "mma.sync.aligned.m16n8k16.row.col.f32.f16.f16.f32 "
        "{%0,%1,%2,%3}, {%4,%5,%6,%7}, {%8,%9}, {%0,%1,%2,%3};"
        : "+f"(c[0]), "+f"(c[1]), "+f"(c[2]), "+f"(c[3])
        : "r"(a[0]), "r"(a[1]), "r"(a[2]), "r"(a[3]), "r"(b[0]), "r"(b[1]));
}
__device__ __forceinline__ void cp16(uint32_t s, const void* g) {
    asm volatile("cp.async.cg.shared.global [%0], [%1], 16;" :: "r"(s), "l"(g));
}

__global__ void __launch_bounds__(256, 2)
gemm_fp16p(int ktiles, int ktstride, size_t czstride,
           const uint32_t* __restrict__ At,
           const uint32_t* __restrict__ Bt,
           float* __restrict__ C, int ldc,
           const float* __restrict__ bias)
{
    const int MFRAG = 4;
    const int NFRAG = 4;
    const int TILE = 2048;

    extern __shared__ __align__(16) uint32_t smem[];
    uint32_t* AsF = smem;
    uint32_t* BsF = smem + 4 * TILE;

    int tid = threadIdx.x;
    int lane = tid & 31;
    int warp = tid >> 5;
    int warp_m = warp >> 2;
    int warp_n = warp & 3;

    int br = blockIdx.y;
    int bc = blockIdx.x;
    int kt0 = blockIdx.z * ktiles;

    const uint4* Ab = (const uint4*)At + ((size_t)br * ktstride + kt0) * (TILE / 4);
    const uint4* Bb = (const uint4*)Bt + ((size_t)bc * ktstride + kt0) * (TILE / 4);
    C += (size_t)blockIdx.z * czstride;

    uint32_t sbase = (uint32_t)__cvta_generic_to_shared(smem);
    uint32_t sb_b = sbase + 4 * TILE * 4;

    auto issue = [&](int t) {
        int slot = t & 3;
        const uint4* An = Ab + (size_t)t * (TILE / 4);
        const uint4* Bn = Bb + (size_t)t * (TILE / 4);
        uint32_t a0 = sbase + slot * (TILE * 4) + tid * 16;
        cp16(a0, An + tid);
        cp16(a0 + 4096, An + tid + 256);
        uint32_t b0 = sb_b + slot * (TILE * 4) + tid * 16;
        cp16(b0, Bn + tid);
        cp16(b0 + 4096, Bn + tid + 256);
        asm volatile("cp.async.commit_group;" ::: "memory");
    };

    issue(0);
    if (ktiles > 1) issue(1);
    if (ktiles > 2) issue(2);

    float acc[MFRAG][NFRAG][4];
    #pragma unroll
    for (int mi = 0; mi < MFRAG; mi++)
        #pragma unroll
        for (int ni = 0; ni < NFRAG; ni++)
            #pragma unroll
            for (int j = 0; j < 4; j++) acc[mi][ni][j] = 0.0f;

    for (int t = 0; t < ktiles; t++) {
        int rem = ktiles - 1 - t;
        if (rem >= 2)      asm volatile("cp.async.wait_group 2;" ::: "memory");
        else if (rem == 1) asm volatile("cp.async.wait_group 1;" ::: "memory");
        else               asm volatile("cp.async.wait_group 0;" ::: "memory");
        __syncthreads();

        if (t + 3 < ktiles) issue(t + 3);

        int slot = t & 3;
        const uint32_t* As = AsF + slot * TILE;
        const uint32_t* Bs = BsF + slot * TILE;

        #pragma unroll
        for (int s = 0; s < 2; s++) {
            uint32_t afr[MFRAG][4];
            uint32_t bfr[NFRAG][2];
            #pragma unroll
            for (int mi = 0; mi < MFRAG; mi++) {
                int t8 = warp_m * MFRAG + mi;
                uint4 fa = *(const uint4*)&As[(((s << 3) + t8) * 32 + lane) * 4];
                afr[mi][0] = fa.x; afr[mi][1] = fa.y;
                afr[mi][2] = fa.z; afr[mi][3] = fa.w;
            }
            #pragma unroll
            for (int ni2 = 0; ni2 < NFRAG / 2; ni2++) {
                int u2 = warp_n * (NFRAG / 2) + ni2;
                uint4 fb = *(const uint4*)&Bs[(((s << 3) + u2) * 32 + lane) * 4];
                bfr[2 * ni2][0]     = fb.x;
                bfr[2 * ni2][1]     = fb.y;
                bfr[2 * ni2 + 1][0] = fb.z;
                bfr[2 * ni2 + 1][1] = fb.w;
            }
            #pragma unroll
            for (int mi = 0; mi < MFRAG; mi++)
                #pragma unroll
                for (int ni = 0; ni < NFRAG; ni++)
                    mma_f16(acc[mi][ni], afr[mi], bfr[ni]);
        }
    }

    int qm = lane >> 2;
    int qk = lane & 3;
    #pragma unroll
    for (int mi = 0; mi < MFRAG; mi++) {
        int r = br * 128 + warp_m * 64 + mi * 16 + qm;
        #pragma unroll
        for (int ni = 0; ni < NFRAG; ni++) {
            int c = bc * 128 + warp_n * 32 + ni * 8 + 2 * qk;
            float2 v0 = make_float2(acc[mi][ni][0], acc[mi][ni][1]);
            float2 v1 = make_float2(acc[mi][ni][2], acc[mi][ni][3]);
            if (bias) {
                float2 bb = *(const float2*)&bias[c];
                v0.x += bb.x; v0.y += bb.y;
                v1.x += bb.x; v1.y += bb.y;
            }
            *(float2*)&C[(size_t)r * ldc + c] = v0;
            *(float2*)&C[(size_t)(r + 8) * ldc + c] = v1;
        }
    }
}

// ------------------------------ host orchestration ---------------------------
extern "C" void kernel_launch(void* const* d_in, const int* in_sizes, int n_in,
                              void* d_out, int out_size)
{
    const float* x       = (const float*)d_in[0];
    const int*   eidx    = (const int*)  d_in[1];
    const float* sage_Wl = (const float*)d_in[2];
    const float* sage_bl = (const float*)d_in[3];
    const float* sage_Wr = (const float*)d_in[4];
    const float* gcn1_W  = (const float*)d_in[5];
    const float* gcn1_b  = (const float*)d_in[6];
    const float* gcn2_W  = (const float*)d_in[7];
    const float* gcn2_b  = (const float*)d_in[8];
    const float* fc1_W   = (const float*)d_in[9];
    const float* fc1_b   = (const float*)d_in[10];
    const float* fc2_W   = (const float*)d_in[11];
    const float* fc2_b   = (const float*)d_in[12];
    const float* out_W   = (const float*)d_in[13];
    const float* out_b   = (const float*)d_in[14];
    float* out = (float*)d_out;

    const int* src = eidx;
    const int* dst = eidx + EE;

    float *P, *A, *B, *C, *D, *E;
    uint32_t *Xt, *Wt, *Ht, *OWt;
    cudaGetSymbolAddress((void**)&P, g_P);
    cudaGetSymbolAddress((void**)&A, g_A);
    cudaGetSymbolAddress((void**)&B, g_B);
    cudaGetSymbolAddress((void**)&C, g_C);
    cudaGetSymbolAddress((void**)&D, g_D);
    cudaGetSymbolAddress((void**)&E, g_E);
    cudaGetSymbolAddress((void**)&Xt, g_Xt);
    cudaGetSymbolAddress((void**)&Wt, g_Wt);
    cudaGetSymbolAddress((void**)&Ht, g_Ht);
    cudaGetSymbolAddress((void**)&OWt, g_OWt);

    const int TPB = 256;
    const int GSMEM = 8 * 2048 * 4;   // 64KB: 4-slot A+B ring
    cudaFuncSetAttribute(gemm_fp16p, cudaFuncAttributeMaxDynamicSharedMemorySize, GSMEM);

    // CSR build (separate scan + chip-wide fill)
    k_csr<<<1, 1024>>>(dst);
    k_fill<<<(EE + TPB - 1) / TPB, TPB>>>(src, dst);

    // pack operands (fp16 fragment-major); packAh smem-staged + coalesced
    k_packAh<<<(NN / 128) * (NN / 32), 256>>>(x, Xt, NN);
    k_packBh<<<NN * 512 / 2 / TPB, TPB>>>(sage_Wl, sage_Wr, 256, NN, 256, Wt);
    k_packBh<<<128 * 16384 / 2 / TPB, TPB>>>(out_W, out_W, 16384, 128, 16384, OWt);

    // P = x @ [Wl | Wr], split-K=2: grid (4,32,2), 64 k-tiles of 32 each
    {
        dim3 grid(512 / 128, NN / 128, 2);
        gemm_fp16p<<<grid, 256, GSMEM>>>(64, 128, (size_t)NN * 512, Xt, Wt, P, 512, nullptr);
    }
    k_padd<<<NN * 128 / TPB, TPB>>>();

    // SAGE (gather, fused combine) -> B
    k_sage_gather<<<NN * 64 / TPB, TPB>>>(sage_bl);

    // GCN1: hw -> C, gather+bias+relu -> A
    {
        dim3 grid(256 / 64, NN / 64);
        sgemm64<<<grid, 256>>>(NN, 256, 256, B, 256, gcn1_W, 256, C, 256);
    }
    k_gcn_gather<<<NN * 64 / TPB, TPB>>>(C, gcn1_b, A, 6);

    // GCN2: hw -> D, gather+bias+relu -> E
    {
        dim3 grid(128 / 64, NN / 64);
        sgemm64<<<grid, 256>>>(NN, 128, 256, A, 256, gcn2_W, 128, D, 128);
    }
    k_gcn_gather<<<NN * 32 / TPB, TPB>>>(D, gcn2_b, E, 5);

    // fused fc1+fc2: E -> C
    k_fc12<<<NN / 64, 256>>>(E, fc1_W, fc1_b, fc2_W, fc2_b, C);

    // head GEMM (4096 x 16384 x 128): 4 k-tiles
    k_packAh<<<(NN / 128) * (128 / 32), 256>>>(C, Ht, 128);
    {
        dim3 grid(16384 / 128, NN / 128, 1);
        gemm_fp16p<<<grid, 256, GSMEM>>>(4, 4, 0, Ht, OWt, out, 16384, out_b);
    }
}